// round 1
// baseline (speedup 1.0000x reference)
#include <cuda_runtime.h>
#include <math.h>

#define CC 128
#define MID 8
#define SB 32      // 32 blocks per spatial dim
#define SPD 64     // full spatial dim

// scratch (allocation-free rule: __device__ globals)
__device__ float g_gap[2 * CC];
__device__ float g_gmod[2 * CC];

#define TWO_SQRT2 2.8284271247461903f

// ---------------------------------------------------------------------------
// Kernel 1: gap[b,c] = mean over 32^3 of x_sum = (2*sqrt(2)/32768) * sum corners
// one CTA per (b,c) -> deterministic reduction
// ---------------------------------------------------------------------------
__global__ __launch_bounds__(256) void k_gap(const float* __restrict__ x) {
    int bc = blockIdx.x;  // 0..255  (b*128 + c)
    const float* base = x + (size_t)bc * (SPD * SPD * SPD);
    float sum = 0.f;
    for (int i = threadIdx.x; i < SB * SB * SB; i += 256) {
        int d = i >> 10;
        int h = (i >> 5) & 31;
        int w = i & 31;
        sum += base[((size_t)(2 * d) * SPD + (2 * h)) * SPD + 2 * w];
    }
    __shared__ float red[256];
    red[threadIdx.x] = sum;
    __syncthreads();
    for (int s = 128; s > 0; s >>= 1) {
        if (threadIdx.x < s) red[threadIdx.x] += red[threadIdx.x + s];
        __syncthreads();
    }
    if (threadIdx.x == 0)
        g_gap[bc] = red[0] * (TWO_SQRT2 / 32768.0f);
}

// ---------------------------------------------------------------------------
// Kernel 2: global MLP:  g[b,c] = gb2[c] + sum_m gw2[c,m] * relu(gb1[m] + sum_c' gw1[m,c'] gap[b,c'])
// one CTA per batch, 128 threads
// ---------------------------------------------------------------------------
__global__ __launch_bounds__(128) void k_gmlp(const float* __restrict__ gw1,
                                              const float* __restrict__ gb1,
                                              const float* __restrict__ gw2,
                                              const float* __restrict__ gb2) {
    int b = blockIdx.x;
    int t = threadIdx.x;  // 0..127
    __shared__ float gap_s[CC];
    __shared__ float hid[MID];
    gap_s[t] = g_gap[b * CC + t];
    __syncthreads();
    if (t < MID) {
        float a = gb1[t];
        #pragma unroll 8
        for (int c = 0; c < CC; c++) a += gw1[t * CC + c] * gap_s[c];
        hid[t] = fmaxf(a, 0.f);
    }
    __syncthreads();
    float a = gb2[t];
    #pragma unroll
    for (int m = 0; m < MID; m++) a += gw2[t * MID + m] * hid[m];
    g_gmod[b * CC + t] = a;
}

// ---------------------------------------------------------------------------
// Kernel 3: per (b, d, h) CTA — local MLP over 128 channels x 32 w-blocks,
// then blend: out = w*x + (1-w)*block_mean  (per 2x2x2 block)
// ---------------------------------------------------------------------------
__global__ __launch_bounds__(256) void k_main(const float* __restrict__ x,
                                              const float* __restrict__ lw1,
                                              const float* __restrict__ lb1,
                                              const float* __restrict__ lw2,
                                              const float* __restrict__ lb2,
                                              float* __restrict__ out) {
    int bid = blockIdx.x;          // 0..2047
    int b = bid >> 10;
    int d = (bid >> 5) & 31;       // z-block
    int h = bid & 31;              // y-block
    int t = threadIdx.x;

    __shared__ float s_s[CC][SB];      // 16 KB: x_sum values, later reused for gate w
    __shared__ float s_hid[MID][SB];   // 1 KB
    __shared__ float s_lw1[MID * CC];  // 4 KB
    __shared__ float s_lw2[CC * MID];  // 4 KB
    __shared__ float s_g[CC];
    __shared__ float s_lb2[CC];

    // preload weights
    for (int i = t; i < MID * CC; i += 256) s_lw1[i] = lw1[i];
    for (int i = t; i < CC * MID; i += 256) s_lw2[i] = lw2[i];
    if (t < CC) {
        s_g[t]   = g_gmod[b * CC + t];
        s_lb2[t] = lb2[t];
    }

    const float* xb = x + (size_t)b * CC * SPD * SPD * SPD;

    // load x_sum = 2*sqrt(2) * corner: 128 channels x 32 w-blocks
    for (int i = t; i < CC * SB; i += 256) {
        int c = i >> 5;
        int w = i & 31;
        s_s[c][w] = TWO_SQRT2 *
            xb[(((size_t)c * SPD + 2 * d) * SPD + 2 * h) * SPD + 2 * w];
    }
    __syncthreads();

    // hidden layer: exactly 256 (m,w) pairs
    {
        int m = t >> 5;      // 0..7
        int w = t & 31;
        float a = lb1[m];
        const float* wrow = &s_lw1[m * CC];
        #pragma unroll 8
        for (int c = 0; c < CC; c++) a += wrow[c] * s_s[c][w];
        s_hid[m][w] = fmaxf(a, 0.f);
    }
    __syncthreads();

    // gate w[c][w] = sigmoid(g[c] + l[c][w]); overwrite s_s
    for (int i = t; i < CC * SB; i += 256) {
        int c = i >> 5;
        int w = i & 31;
        float a = s_lb2[c];
        #pragma unroll
        for (int m = 0; m < MID; m++) a += s_lw2[c * MID + m] * s_hid[m][w];
        a += s_g[c];
        s_s[c][w] = 1.0f / (1.0f + __expf(-a));
    }
    __syncthreads();

    // blend pass: thread = (csub, wb); 8 channels per iter, 16 iters
    float* ob = out + (size_t)b * CC * SPD * SPD * SPD;
    int wb = t & 31;
    int csub = t >> 5;  // 0..7
    #pragma unroll 1
    for (int cg = 0; cg < CC; cg += 8) {
        int c = cg + csub;
        size_t base = (((size_t)c * SPD + 2 * d) * SPD + 2 * h) * SPD + 2 * wb;
        float2 a00 = *(const float2*)(xb + base);
        float2 a01 = *(const float2*)(xb + base + SPD);
        float2 a10 = *(const float2*)(xb + base + SPD * SPD);
        float2 a11 = *(const float2*)(xb + base + SPD * SPD + SPD);
        float mean = (a00.x + a00.y + a01.x + a01.y +
                      a10.x + a10.y + a11.x + a11.y) * 0.125f;
        float wa = s_s[c][wb];
        float om = (1.0f - wa) * mean;
        a00.x = fmaf(wa, a00.x, om); a00.y = fmaf(wa, a00.y, om);
        a01.x = fmaf(wa, a01.x, om); a01.y = fmaf(wa, a01.y, om);
        a10.x = fmaf(wa, a10.x, om); a10.y = fmaf(wa, a10.y, om);
        a11.x = fmaf(wa, a11.x, om); a11.y = fmaf(wa, a11.y, om);
        *(float2*)(ob + base)                 = a00;
        *(float2*)(ob + base + SPD)           = a01;
        *(float2*)(ob + base + SPD * SPD)     = a10;
        *(float2*)(ob + base + SPD * SPD + SPD) = a11;
    }
}

// ---------------------------------------------------------------------------
extern "C" void kernel_launch(void* const* d_in, const int* in_sizes, int n_in,
                              void* d_out, int out_size) {
    const float* x   = (const float*)d_in[0];
    const float* gw1 = (const float*)d_in[1];
    const float* gb1 = (const float*)d_in[2];
    const float* gw2 = (const float*)d_in[3];
    const float* gb2 = (const float*)d_in[4];
    const float* lw1 = (const float*)d_in[5];
    const float* lb1 = (const float*)d_in[6];
    const float* lw2 = (const float*)d_in[7];
    const float* lb2 = (const float*)d_in[8];
    float* out = (float*)d_out;

    k_gap<<<2 * CC, 256>>>(x);
    k_gmlp<<<2, 128>>>(gw1, gb1, gw2, gb2);
    k_main<<<2 * SB * SB, 256>>>(x, lw1, lb1, lw2, lb2, out);
}